// round 11
// baseline (speedup 1.0000x reference)
#include <cuda_runtime.h>
#include <cstdint>
#include <mma.h>
using namespace nvcuda;

#define N_NODES 100000
#define F 128
#define SCAN_C 512
#define SCAN_NB ((N_NODES + SCAN_C - 1) / SCAN_C)   // 196

// Scratch (device globals — no runtime allocation allowed)
__device__ float g_agg[N_NODES * F];     // mean-aggregated, tf32-rounded
__device__ float g_h1[N_NODES * F];      // layer-1 out, tf32-rounded
__device__ float g_xr[N_NODES * F];      // tf32-rounded copy of x
__device__ float g_w1s[F * F], g_w1n[F * F], g_w2s[F * F], g_w2n[F * F];
__device__ int   g_deg[N_NODES];
__device__ int   g_row_start[N_NODES];
__device__ int   g_cursor[N_NODES];
__device__ int   g_blocksum[SCAN_NB];
__device__ int   g_blockoff[SCAN_NB];
__device__ int   g_csr_src[2000000];

__device__ __forceinline__ float tf32r(float v) {
    float r;
    asm("cvt.rna.tf32.f32 %0, %1;" : "=f"(r) : "f"(v));
    return r;
}

// ---------------------------------------------------------------------------
// Pre-round weights (4 x 16384 floats) into scratch
__global__ void round_w_kernel(const float* __restrict__ W1s,
                               const float* __restrict__ W1n,
                               const float* __restrict__ W2s,
                               const float* __restrict__ W2n) {
    int i = blockIdx.x * blockDim.x + threadIdx.x;
    if (i < F * F) {
        g_w1s[i] = tf32r(W1s[i]);
        g_w1n[i] = tf32r(W1n[i]);
        g_w2s[i] = tf32r(W2s[i]);
        g_w2n[i] = tf32r(W2n[i]);
    }
}

// Pre-round x into g_xr
__global__ void round_x_kernel(const float* __restrict__ x) {
    int i = blockIdx.x * blockDim.x + threadIdx.x;
    int stride = gridDim.x * blockDim.x;
    const int total4 = N_NODES * F / 4;
    for (int j = i; j < total4; j += stride) {
        float4 v = reinterpret_cast<const float4*>(x)[j];
        v.x = tf32r(v.x); v.y = tf32r(v.y); v.z = tf32r(v.z); v.w = tf32r(v.w);
        reinterpret_cast<float4*>(g_xr)[j] = v;
    }
}

// ---------------------------------------------------------------------------
__global__ void deg_zero_kernel() {
    int i = blockIdx.x * blockDim.x + threadIdx.x;
    if (i < N_NODES) g_deg[i] = 0;
}

__global__ void deg_kernel(const int* __restrict__ dst, int E) {
    int i = blockIdx.x * blockDim.x + threadIdx.x;
    if (i < E) atomicAdd(&g_deg[dst[i]], 1);
}

// --------------------------- CSR scan ---------------------------------------
__global__ void scan_phaseA() {
    __shared__ int s[SCAN_C];
    int t = threadIdx.x;
    int i = blockIdx.x * SCAN_C + t;
    s[t] = (i < N_NODES) ? g_deg[i] : 0;
    __syncthreads();
    for (int off = SCAN_C / 2; off > 0; off >>= 1) {
        if (t < off) s[t] += s[t + off];
        __syncthreads();
    }
    if (t == 0) g_blocksum[blockIdx.x] = s[0];
}

__global__ void scan_phaseB() {
    __shared__ int s[512];
    int t = threadIdx.x;
    s[t] = (t < SCAN_NB) ? g_blocksum[t] : 0;
    __syncthreads();
    for (int off = 1; off < 512; off <<= 1) {
        int v = s[t] + ((t >= off) ? s[t - off] : 0);
        __syncthreads();
        s[t] = v;
        __syncthreads();
    }
    if (t < SCAN_NB) g_blockoff[t] = s[t] - g_blocksum[t];
}

__global__ void scan_phaseC() {
    __shared__ int s[SCAN_C];
    int t = threadIdx.x;
    int i = blockIdx.x * SCAN_C + t;
    int own = (i < N_NODES) ? g_deg[i] : 0;
    s[t] = own;
    __syncthreads();
    for (int off = 1; off < SCAN_C; off <<= 1) {
        int v = s[t] + ((t >= off) ? s[t - off] : 0);
        __syncthreads();
        s[t] = v;
        __syncthreads();
    }
    if (i < N_NODES) {
        int start = g_blockoff[blockIdx.x] + s[t] - own;
        g_row_start[i] = start;
        g_cursor[i] = start;
    }
}

__global__ void fill_kernel(const int* __restrict__ src,
                            const int* __restrict__ dst, int E) {
    int i = blockIdx.x * blockDim.x + threadIdx.x;
    if (i < E) {
        int d = dst[i];
        int pos = atomicAdd(&g_cursor[d], 1);
        g_csr_src[pos] = src[i];
    }
}

// ---------------------------------------------------------------------------
// Gather mean: one warp per dst node, float4 per lane. Output tf32-rounded.
// ---------------------------------------------------------------------------
__global__ void gather_kernel(const float* __restrict__ feat) {
    int w = (blockIdx.x * blockDim.x + threadIdx.x) >> 5;
    int lane = threadIdx.x & 31;
    if (w >= N_NODES) return;
    int start = g_row_start[w];
    int deg = g_deg[w];
    float4 acc = make_float4(0.f, 0.f, 0.f, 0.f);
    int e = 0;
    for (; e + 2 <= deg; e += 2) {
        int s0 = g_csr_src[start + e];
        int s1 = g_csr_src[start + e + 1];
        float4 v0 = reinterpret_cast<const float4*>(feat + (size_t)s0 * F)[lane];
        float4 v1 = reinterpret_cast<const float4*>(feat + (size_t)s1 * F)[lane];
        acc.x += v0.x + v1.x; acc.y += v0.y + v1.y;
        acc.z += v0.z + v1.z; acc.w += v0.w + v1.w;
    }
    if (e < deg) {
        int s0 = g_csr_src[start + e];
        float4 v0 = reinterpret_cast<const float4*>(feat + (size_t)s0 * F)[lane];
        acc.x += v0.x; acc.y += v0.y; acc.z += v0.z; acc.w += v0.w;
    }
    float inv = (deg > 0) ? 1.f / (float)deg : 0.f;
    acc.x = tf32r(acc.x * inv); acc.y = tf32r(acc.y * inv);
    acc.z = tf32r(acc.z * inv); acc.w = tf32r(acc.w * inv);
    reinterpret_cast<float4*>(g_agg + (size_t)w * F)[lane] = acc;
}

// ---------------------------------------------------------------------------
// TF32 tensor-core fused SAGE GEMM (inputs pre-rounded to tf32 — no in-loop
// converts): out = act([A0|A1] @ [Ws;Wn] + bias)
// Block 128x128, K=256 in 8 chunks of 32. 8 warps: 4(M) x 2(N), warp 32x64.
// ---------------------------------------------------------------------------
#define ARENA_BYTES 70656

__device__ __forceinline__ void cp_async16(uint32_t smem, const void* gptr, int srcsize) {
    asm volatile("cp.async.cg.shared.global [%0], [%1], 16, %2;"
                 :: "r"(smem), "l"(gptr), "r"(srcsize));
}

__global__ __launch_bounds__(256, 2)
void gemm_tc_kernel(const float* __restrict__ A0, const float* __restrict__ A1,
                    const float* __restrict__ Ws, const float* __restrict__ Wn,
                    const float* __restrict__ bias, float* __restrict__ out,
                    int relu_round) {
    extern __shared__ __align__(16) char arena[];
    float* Asf = (float*)arena;              // [2][128][36]
    float* Bsf = (float*)(arena + 36864);    // [2][32][132]
    float* Csf = (float*)arena;              // [128][132] epilogue reuse

    const int tid = threadIdx.x;
    const int row0 = blockIdx.x * 128;
    const int w = tid >> 5;
    const int wm = w & 3;
    const int wn = w >> 2;

    const uint32_t sA = (uint32_t)__cvta_generic_to_shared(Asf);
    const uint32_t sB = (uint32_t)__cvta_generic_to_shared(Bsf);

    wmma::fragment<wmma::accumulator, 16, 16, 8, float> cfrag[2][4];
#pragma unroll
    for (int i = 0; i < 2; i++)
#pragma unroll
        for (int j = 0; j < 4; j++) wmma::fill_fragment(cfrag[i][j], 0.f);

#define LOAD_CHUNK_TC(c, buf)                                                  \
    {                                                                          \
        const float* Ap = ((c) < 4) ? A0 : A1;                                 \
        const float* Wp = ((c) < 4) ? Ws : Wn;                                 \
        int kb = ((c) & 3) * 32;                                               \
        _Pragma("unroll")                                                      \
        for (int j = 0; j < 4; j++) {                                          \
            int i = tid + j * 256;                                             \
            int row = i >> 3, q = i & 7;                                       \
            int grow = row0 + row;                                             \
            int ok = grow < N_NODES;                                           \
            const float* srcA = Ap + (size_t)(ok ? grow : 0) * F + kb + q * 4; \
            cp_async16(sA + (uint32_t)((buf)*4608 + row * 36 + q * 4) * 4,     \
                       srcA, ok ? 16 : 0);                                     \
            int kr = i >> 5, qq = i & 31;                                      \
            cp_async16(sB + (uint32_t)((buf)*4224 + kr * 132 + qq * 4) * 4,    \
                       Wp + (size_t)(kb + kr) * F + qq * 4, 16);               \
        }                                                                      \
        asm volatile("cp.async.commit_group;");                                \
    }

    LOAD_CHUNK_TC(0, 0);
    asm volatile("cp.async.wait_group 0;");
    __syncthreads();

    for (int c = 0; c < 8; c++) {
        const int buf = c & 1;
        if (c < 7) LOAD_CHUNK_TC(c + 1, buf ^ 1);

#pragma unroll
        for (int ks = 0; ks < 4; ks++) {
            wmma::fragment<wmma::matrix_a, 16, 16, 8, wmma::precision::tf32,
                           wmma::row_major> af[2];
            wmma::fragment<wmma::matrix_b, 16, 16, 8, wmma::precision::tf32,
                           wmma::row_major> bf[4];
#pragma unroll
            for (int i = 0; i < 2; i++)
                wmma::load_matrix_sync(
                    af[i], Asf + buf * 4608 + (wm * 32 + i * 16) * 36 + ks * 8, 36);
#pragma unroll
            for (int j = 0; j < 4; j++)
                wmma::load_matrix_sync(
                    bf[j], Bsf + buf * 4224 + (ks * 8) * 132 + wn * 64 + j * 16, 132);
#pragma unroll
            for (int i = 0; i < 2; i++)
#pragma unroll
                for (int j = 0; j < 4; j++)
                    wmma::mma_sync(cfrag[i][j], af[i], bf[j], cfrag[i][j]);
        }

        if (c < 7) asm volatile("cp.async.wait_group 0;");
        __syncthreads();
    }

    // Epilogue: C frags -> SMEM, then bias (+relu + tf32-round for layer 1)
#pragma unroll
    for (int i = 0; i < 2; i++)
#pragma unroll
        for (int j = 0; j < 4; j++)
            wmma::store_matrix_sync(
                Csf + (wm * 32 + i * 16) * 132 + wn * 64 + j * 16,
                cfrag[i][j], 132, wmma::mem_row_major);
    __syncthreads();

    {
        int r = tid >> 1;
        int half = tid & 1;
        int grow = row0 + r;
        if (grow < N_NODES) {
            float* o = out + (size_t)grow * F + half * 64;
            const float* cs = Csf + r * 132 + half * 64;
            const float* bp = bias + half * 64;
#pragma unroll
            for (int k = 0; k < 16; k++) {
                float4 v = *reinterpret_cast<const float4*>(cs + k * 4);
                float4 b = *reinterpret_cast<const float4*>(bp + k * 4);
                v.x += b.x; v.y += b.y; v.z += b.z; v.w += b.w;
                if (relu_round) {
                    v.x = tf32r(v.x > 0.f ? v.x : 0.f);
                    v.y = tf32r(v.y > 0.f ? v.y : 0.f);
                    v.z = tf32r(v.z > 0.f ? v.z : 0.f);
                    v.w = tf32r(v.w > 0.f ? v.w : 0.f);
                }
                *reinterpret_cast<float4*>(o + k * 4) = v;
            }
        }
    }
}

// ---------------------------------------------------------------------------
extern "C" void kernel_launch(void* const* d_in, const int* in_sizes, int n_in,
                              void* d_out, int out_size) {
    const float* x   = (const float*)d_in[0];
    const int*   src = (const int*)d_in[1];    // int32 (jax x64 disabled)
    const int*   dst = (const int*)d_in[2];
    const float* W1s = (const float*)d_in[3];
    const float* W1n = (const float*)d_in[4];
    const float* b1  = (const float*)d_in[5];
    const float* W2s = (const float*)d_in[6];
    const float* W2n = (const float*)d_in[7];
    const float* b2  = (const float*)d_in[8];
    float* out = (float*)d_out;
    const int E = in_sizes[1];

    float *h1, *agg, *xr, *w1s, *w1n, *w2s, *w2n;
    cudaGetSymbolAddress((void**)&h1, g_h1);
    cudaGetSymbolAddress((void**)&agg, g_agg);
    cudaGetSymbolAddress((void**)&xr, g_xr);
    cudaGetSymbolAddress((void**)&w1s, g_w1s);
    cudaGetSymbolAddress((void**)&w1n, g_w1n);
    cudaGetSymbolAddress((void**)&w2s, g_w2s);
    cudaGetSymbolAddress((void**)&w2n, g_w2n);

    cudaFuncSetAttribute(gemm_tc_kernel,
                         cudaFuncAttributeMaxDynamicSharedMemorySize, ARENA_BYTES);

    // --- CSR build + pre-rounding ---
    deg_zero_kernel<<<(N_NODES + 255) / 256, 256>>>();
    deg_kernel<<<(E + 255) / 256, 256>>>(dst, E);
    scan_phaseA<<<SCAN_NB, SCAN_C>>>();
    scan_phaseB<<<1, 512>>>();
    scan_phaseC<<<SCAN_NB, SCAN_C>>>();
    fill_kernel<<<(E + 255) / 256, 256>>>(src, dst, E);
    round_w_kernel<<<(F * F + 255) / 256, 256>>>(W1s, W1n, W2s, W2n);
    round_x_kernel<<<2048, 256>>>(x);

    const int gather_blocks = (N_NODES * 32 + 255) / 256;
    const int gemm_blocks = (N_NODES + 127) / 128;

    // --- layer 1 ---  (gather reads full-precision x; GEMM uses rounded xr)
    gather_kernel<<<gather_blocks, 256>>>(x);
    gemm_tc_kernel<<<gemm_blocks, 256, ARENA_BYTES>>>(xr, agg, w1s, w1n, b1, h1, 1);
    // --- layer 2 ---
    gather_kernel<<<gather_blocks, 256>>>(h1);
    gemm_tc_kernel<<<gemm_blocks, 256, ARENA_BYTES>>>(h1, agg, w2s, w2n, b2, out, 0);
}